// round 9
// baseline (speedup 1.0000x reference)
#include <cuda_runtime.h>
#include <stdint.h>

#define R_NODES   256
#define N_STEPS   512
#define M_SAMP    512
#define OUT_DIM   10
#define LUT_WORDS 8192            // 2^18 bits / 32
#define NPC       4               // samples per CTA
#define N_CTA     (M_SAMP / NPC)  // 128 CTAs -> ~1 per SM
#define RB_BYTES  272             // s8 state row stride: word banks 4g+tg distinct

// Scratch: __device__ globals (no allocation allowed)
__device__ unsigned g_lut_bits[R_NODES * LUT_WORDS]; // 8 MB bit-packed LUT
__device__ unsigned g_x_bits[M_SAMP * N_STEPS];      // 1 MB bit-packed inputs

// ---------------------------------------------------------------------------
// Pack LUT (flat): word w, bit b = lut[w*32 + b]. MLP=32 load stage then ballots.
// ---------------------------------------------------------------------------
__global__ void pack_lut_kernel(const int* __restrict__ lut) {
    const int warp_g = (blockIdx.x * blockDim.x + threadIdx.x) >> 5;
    const int lane   = threadIdx.x & 31;
    const int w0     = warp_g * 32;
    const unsigned* src = (const unsigned*)lut;
    unsigned v[32];
    #pragma unroll
    for (int i = 0; i < 32; i++)
        v[i] = src[(size_t)(w0 + i) * 32 + lane];
    unsigned myw = 0;
    #pragma unroll
    for (int i = 0; i < 32; i++) {
        unsigned b = __ballot_sync(0xFFFFFFFFu, v[i] & 1u);
        if (i == lane) myw = b;
    }
    g_lut_bits[w0 + lane] = myw;
}

// ---------------------------------------------------------------------------
// Pack x: int32[512][512][4][8] (0/1) -> g_x_bits[m*512 + t], bit i = feature i
// ---------------------------------------------------------------------------
__global__ void pack_x_kernel(const int* __restrict__ x) {
    int w = blockIdx.x * blockDim.x + threadIdx.x;
    if (w >= M_SAMP * N_STEPS) return;
    const uint4* p = (const uint4*)(x + (size_t)w * 32);
    unsigned word = 0;
    #pragma unroll
    for (int j = 0; j < 8; j++) {
        uint4 v = p[j];
        word |= (v.x & 1u) << (4 * j + 0);
        word |= (v.y & 1u) << (4 * j + 1);
        word |= (v.z & 1u) << (4 * j + 2);
        word |= (v.w & 1u) << (4 * j + 3);
    }
    g_x_bits[w] = word;
}

// ---------------------------------------------------------------------------
// m16n8k32 s8 IMMA, s32 accumulate (exact)
// ---------------------------------------------------------------------------
__device__ __forceinline__ void imma16832(int* d, const unsigned* a, unsigned b0, unsigned b1) {
    asm volatile(
        "mma.sync.aligned.m16n8k32.row.col.s32.s8.s8.s32 "
        "{%0,%1,%2,%3}, {%4,%5,%6,%7}, {%8,%9}, {%0,%1,%2,%3};\n"
        : "+r"(d[0]), "+r"(d[1]), "+r"(d[2]), "+r"(d[3])
        : "r"(a[0]), "r"(a[1]), "r"(a[2]), "r"(a[3]), "r"(b0), "r"(b1));
}

// ---------------------------------------------------------------------------
// Reservoir kernel: 128 CTAs x 256 threads, CTA b owns samples [4b, 4b+4).
// Warp w owns nodes [32w, 32w+32). Wp split as prime = 128*hi + lo (both s8);
// A_lo/A_hi register-resident (8 kt x 2 mt x 4 regs each). Per step:
// 32 IMMA -> idx = sum_lo + (sum_hi << 7) (exact s32) -> bit-packed LUT gather
// (L2) -> new s8 state into the double-buffered tile. One barrier per step.
// ---------------------------------------------------------------------------
__global__ void __launch_bounds__(256, 1)
reservoir_kernel(const int* __restrict__ input_nodes,
                 const int* __restrict__ Wres,
                 const int* __restrict__ primes,
                 const int* __restrict__ init_res,
                 const float* __restrict__ readout_W,
                 const float* __restrict__ readout_b,
                 float* __restrict__ out)
{
    __shared__ signed char rb[2][8][RB_BYTES];   // double-buffered state (s8 0/1)
    __shared__ short s_inp[R_NODES];             // node -> input-feature index or -1
    __shared__ int s_innodes[32];                // feature -> node
    __shared__ unsigned char s_plo[R_NODES];     // prime & 127
    __shared__ unsigned char s_phi[R_NODES];     // prime >> 7  (<= 12)
    __shared__ float s_W[OUT_DIM * R_NODES];     // readout weights

    const int tid  = threadIdx.x;
    const int wid  = tid >> 5;
    const int lane = tid & 31;
    const int g    = lane >> 2;                  // MMA row-in-tile / B sample col
    const int tg   = lane & 3;
    const int mbase = blockIdx.x * NPC;

    // ---- shared tables ----
    s_inp[tid] = -1;
    {
        int p = primes[tid];
        s_plo[tid] = (unsigned char)(p & 127);
        s_phi[tid] = (unsigned char)(p >> 7);
    }
    for (int i = tid; i < OUT_DIM * R_NODES; i += 256) s_W[i] = readout_W[i];
    __syncthreads();
    if (tid < 32) {
        int nn = input_nodes[tid];
        s_innodes[tid] = nn;
        s_inp[nn] = (short)tid;
    }

    // ---- A fragments: A_lo / A_hi packed s8, register-resident ----
    unsigned Alo[8][2][4], Ahi[8][2][4];
    const int node_base = wid * 32;
    #pragma unroll
    for (int kt = 0; kt < 8; kt++) {
        #pragma unroll
        for (int mt = 0; mt < 2; mt++) {
            #pragma unroll
            for (int r = 0; r < 4; r++) {
                int row = node_base + mt * 16 + g + ((r & 1) ? 8 : 0);
                int k0  = kt * 32 + tg * 4 + ((r & 2) ? 16 : 0);
                unsigned lo = 0, hi = 0;
                #pragma unroll
                for (int b = 0; b < 4; b++) {
                    int k = k0 + b;
                    if (Wres[row * 256 + k]) {
                        lo |= (unsigned)s_plo[k] << (8 * b);
                        hi |= (unsigned)s_phi[k] << (8 * b);
                    }
                }
                Alo[kt][mt][r] = lo;
                Ahi[kt][mt][r] = hi;
            }
        }
    }

    // ---- init: rows 0-3 = init_res, rows 4-7 = zero (both buffers); then x_0 ----
    {
        signed char v = init_res[tid] ? 1 : 0;
        #pragma unroll
        for (int s = 0; s < NPC; s++) rb[0][s][tid] = v;
        #pragma unroll
        for (int s = NPC; s < 8; s++) { rb[0][s][tid] = 0; rb[1][s][tid] = 0; }
        if (tid < 16) {                          // pad bytes 256..271 zero
            #pragma unroll
            for (int s = 0; s < 8; s++) { rb[0][s][256 + tid] = 0; rb[1][s][256 + tid] = 0; }
        }
    }
    __syncthreads();
    if (tid < NPC * 32) {
        int s = tid >> 5, i = tid & 31;          // sample s, feature i
        unsigned xb = (g_x_bits[(size_t)(mbase + s) * N_STEPS + 0] >> i) & 1u;
        rb[0][s][s_innodes[i]] = (signed char)xb;
    }
    __syncthreads();

    // ---- per-thread gather constants (active lanes: tg < 2) ----
    const bool active = (tg < 2);
    const unsigned* lp[2][2];                    // [mt][rowhalf] LUT row base
    int nodes[2][2];
    bool is_inp[2][2];
    #pragma unroll
    for (int mt = 0; mt < 2; mt++)
        #pragma unroll
        for (int h = 0; h < 2; h++) {
            int n = node_base + mt * 16 + g + h * 8;
            nodes[mt][h]  = n;
            lp[mt][h]     = g_lut_bits + (size_t)n * LUT_WORDS;
            is_inp[mt][h] = (s_inp[n] >= 0);
        }
    const int xs = tid >> 5;                     // x-overwrite role (threads < 128)
    const int xi = tid & 31;
    const int xnode = (tid < NPC * 32) ? s_innodes[xi] : 0;
    const unsigned* xrow = g_x_bits + (size_t)(mbase + (xs & (NPC - 1))) * N_STEPS;

    // ---- 512 sequential steps, one barrier per step ----
    for (int t = 0; t < N_STEPS; t++) {
        const int p = t & 1;
        const bool last = (t == N_STEPS - 1);
        const signed char (*cur)[RB_BYTES] = rb[p];
        signed char (*nxt)[RB_BYTES] = rb[p ^ 1];

        // prefetch next input word while MMAs run
        unsigned xw = 0;
        if (!last && tid < NPC * 32) xw = xrow[t + 1];

        // 2-way split s32 accumulator chains per (mt, comp)
        int dlo[2][2][4], dhi[2][2][4];
        #pragma unroll
        for (int mt = 0; mt < 2; mt++)
            #pragma unroll
            for (int c = 0; c < 2; c++)
                #pragma unroll
                for (int e = 0; e < 4; e++) { dlo[mt][c][e] = 0; dhi[mt][c][e] = 0; }

        #pragma unroll
        for (int kt = 0; kt < 8; kt++) {
            unsigned b0 = *(const unsigned*)&cur[g][kt * 32 + tg * 4];
            unsigned b1 = *(const unsigned*)&cur[g][kt * 32 + tg * 4 + 16];
            imma16832(dlo[0][kt & 1], Alo[kt][0], b0, b1);
            imma16832(dlo[1][kt & 1], Alo[kt][1], b0, b1);
            imma16832(dhi[0][kt & 1], Ahi[kt][0], b0, b1);
            imma16832(dhi[1][kt & 1], Ahi[kt][1], b0, b1);
        }

        if (active) {
            unsigned u[2][4];
            #pragma unroll
            for (int mt = 0; mt < 2; mt++)
                #pragma unroll
                for (int e = 0; e < 4; e++) {
                    int lo = dlo[mt][0][e] + dlo[mt][1][e];
                    int hi = dhi[mt][0][e] + dhi[mt][1][e];
                    u[mt][e] = (unsigned)(lo + (hi << 7));
                }

            // batch up to 8 LUT word loads (skip input nodes unless last step)
            unsigned w[2][4];
            #pragma unroll
            for (int mt = 0; mt < 2; mt++)
                #pragma unroll
                for (int e = 0; e < 4; e++)
                    if (last || !is_inp[mt][e >> 1])
                        w[mt][e] = lp[mt][e >> 1][u[mt][e] >> 5];

            #pragma unroll
            for (int mt = 0; mt < 2; mt++)
                #pragma unroll
                for (int e = 0; e < 4; e++)
                    if (last || !is_inp[mt][e >> 1]) {
                        int samp = tg * 2 + (e & 1);     // 0..3 since tg<2
                        nxt[samp][nodes[mt][e >> 1]] =
                            (signed char)((w[mt][e] >> (u[mt][e] & 31)) & 1u);
                    }
        }

        // x_{t+1} into input nodes of next buffer (threads 0..127)
        if (!last && tid < NPC * 32)
            nxt[xs][xnode] = (signed char)((xw >> xi) & 1u);

        __syncthreads();
    }

    // ---- readout: warps 0-3, warp w -> sample w; final state in rb[0] ----
    if (wid < NPC) {
        float acc[OUT_DIM];
        #pragma unroll
        for (int o = 0; o < OUT_DIM; o++) acc[o] = 0.0f;
        #pragma unroll
        for (int kk = 0; kk < 8; kk++) {
            int k = lane + kk * 32;
            float rv = (float)rb[0][wid][k];
            #pragma unroll
            for (int o = 0; o < OUT_DIM; o++)
                acc[o] += rv * s_W[o * R_NODES + k];
        }
        #pragma unroll
        for (int o = 0; o < OUT_DIM; o++) {
            #pragma unroll
            for (int off = 16; off; off >>= 1)
                acc[o] += __shfl_xor_sync(0xFFFFFFFFu, acc[o], off);
        }
        if (lane == 0) {
            #pragma unroll
            for (int o = 0; o < OUT_DIM; o++)
                out[(mbase + wid) * OUT_DIM + o] = acc[o] + readout_b[o];
        }
    }
}

// ---------------------------------------------------------------------------
// kernel_launch. Inputs: x, input_nodes, lut, W_res, primes, init_res,
// readout_W, readout_b (bool arrays delivered as int32).
// ---------------------------------------------------------------------------
extern "C" void kernel_launch(void* const* d_in, const int* in_sizes, int n_in,
                              void* d_out, int out_size) {
    const int*   x        = (const int*)d_in[0];
    const int*   in_nodes = (const int*)d_in[1];
    const int*   lut      = (const int*)d_in[2];
    const int*   Wres     = (const int*)d_in[3];
    const int*   primes   = (const int*)d_in[4];
    const int*   init_res = (const int*)d_in[5];
    const float* rW       = (const float*)d_in[6];
    const float* rb       = (const float*)d_in[7];
    float*       out      = (float*)d_out;

    pack_lut_kernel<<<(R_NODES * LUT_WORDS) / (32 * 8), 256>>>(lut);
    pack_x_kernel<<<(M_SAMP * N_STEPS) / 256, 256>>>(x);
    reservoir_kernel<<<N_CTA, 256>>>(in_nodes, Wres, primes, init_res, rW, rb, out);
}

// round 10
// speedup vs baseline: 2.2257x; 2.2257x over previous
#include <cuda_runtime.h>
#include <cuda_fp16.h>
#include <stdint.h>

#define R_NODES   256
#define N_STEPS   512
#define M_SAMP    512
#define OUT_DIM   10
#define LUT_WORDS 8192            // 2^18 bits / 32
#define NPC       4               // samples per CTA
#define N_CTA     (M_SAMP / NPC)  // 128 CTAs -> ~1 per SM
#define RB_STRIDE 264             // halfs per row: word banks (g*132+tg)%32 distinct
#define MAGIC_F   8388608.0f      // 2^23: accumulator mantissa low 23 bits == integer sum

// Scratch: __device__ globals (no allocation allowed)
__device__ unsigned g_lut_bits[R_NODES * LUT_WORDS]; // 8 MB bit-packed LUT
__device__ unsigned g_x_bits[M_SAMP * N_STEPS];      // 1 MB bit-packed inputs

// ---------------------------------------------------------------------------
// Pack LUT (flat): word w, bit b = lut[w*32 + b]. MLP=32 load stage then ballots.
// ---------------------------------------------------------------------------
__global__ void pack_lut_kernel(const int* __restrict__ lut) {
    const int warp_g = (blockIdx.x * blockDim.x + threadIdx.x) >> 5;
    const int lane   = threadIdx.x & 31;
    const int w0     = warp_g * 32;
    const unsigned* src = (const unsigned*)lut;
    unsigned v[32];
    #pragma unroll
    for (int i = 0; i < 32; i++)
        v[i] = src[(size_t)(w0 + i) * 32 + lane];
    unsigned myw = 0;
    #pragma unroll
    for (int i = 0; i < 32; i++) {
        unsigned b = __ballot_sync(0xFFFFFFFFu, v[i] & 1u);
        if (i == lane) myw = b;
    }
    g_lut_bits[w0 + lane] = myw;
}

// ---------------------------------------------------------------------------
// Pack x: int32[512][512][4][8] (0/1) -> g_x_bits[m*512 + t], bit i = feature i
// ---------------------------------------------------------------------------
__global__ void pack_x_kernel(const int* __restrict__ x) {
    int w = blockIdx.x * blockDim.x + threadIdx.x;
    if (w >= M_SAMP * N_STEPS) return;
    const uint4* p = (const uint4*)(x + (size_t)w * 32);
    unsigned word = 0;
    #pragma unroll
    for (int j = 0; j < 8; j++) {
        uint4 v = p[j];
        word |= (v.x & 1u) << (4 * j + 0);
        word |= (v.y & 1u) << (4 * j + 1);
        word |= (v.z & 1u) << (4 * j + 2);
        word |= (v.w & 1u) << (4 * j + 3);
    }
    g_x_bits[w] = word;
}

// ---------------------------------------------------------------------------
// m16n8k16 fp16 MMA, fp32 accumulate (exact for our integer ranges)
// ---------------------------------------------------------------------------
__device__ __forceinline__ void mma16816(float* d, const unsigned* a, unsigned b0, unsigned b1) {
    asm volatile(
        "mma.sync.aligned.m16n8k16.row.col.f32.f16.f16.f32 "
        "{%0,%1,%2,%3}, {%4,%5,%6,%7}, {%8,%9}, {%0,%1,%2,%3};\n"
        : "+f"(d[0]), "+f"(d[1]), "+f"(d[2]), "+f"(d[3])
        : "f"(d[0]), "f"(d[1]), "f"(d[2]), "f"(d[3]),
          "r"(a[0]), "r"(a[1]), "r"(a[2]), "r"(a[3]), "r"(b0), "r"(b1)
        : );
}

// (correct operand form — no duplicate read list)
__device__ __forceinline__ void mma16816b(float* d, const unsigned* a, unsigned b0, unsigned b1) {
    asm volatile(
        "mma.sync.aligned.m16n8k16.row.col.f32.f16.f16.f32 "
        "{%0,%1,%2,%3}, {%4,%5,%6,%7}, {%8,%9}, {%0,%1,%2,%3};\n"
        : "+f"(d[0]), "+f"(d[1]), "+f"(d[2]), "+f"(d[3])
        : "r"(a[0]), "r"(a[1]), "r"(a[2]), "r"(a[3]), "r"(b0), "r"(b1));
}

// ---------------------------------------------------------------------------
// Reservoir kernel: 128 CTAs x 256 threads, CTA b owns samples [4b, 4b+4).
// Warp w owns nodes [32w, 32w+32) (A in 128 regs). B rows hold samples
// [0,1,2,3,0,1,2,3] so ALL D columns are valid: lane (g,tg) gathers for
// nodes of m-tile (tg>>1) and samples {2*(tg&1), 2*(tg&1)+1} -> 4 loads/lane,
// every (node,sample) covered exactly once. mt0-chain -> issue mt0 loads ->
// mt1-chain (overlaps L2 latency) -> issue mt1 loads -> consume + store.
// ---------------------------------------------------------------------------
__global__ void __launch_bounds__(256, 1)
reservoir_kernel(const int* __restrict__ input_nodes,
                 const int* __restrict__ Wres,
                 const int* __restrict__ primes,
                 const int* __restrict__ init_res,
                 const float* __restrict__ readout_W,
                 const float* __restrict__ readout_b,
                 float* __restrict__ out)
{
    __shared__ __half rb[2][8][RB_STRIDE];       // double-buffered; rows s and s+4 mirror
    __shared__ short s_inp[R_NODES];
    __shared__ int s_innodes[32];
    __shared__ unsigned short s_ph[R_NODES];
    __shared__ float s_W[OUT_DIM * R_NODES];

    const int tid  = threadIdx.x;
    const int wid  = tid >> 5;
    const int lane = tid & 31;
    const int g    = lane >> 2;
    const int tg   = lane & 3;
    const int mbase = blockIdx.x * NPC;
    const __half ONE  = __ushort_as_half(0x3C00);
    const __half ZERO = __ushort_as_half(0x0000);

    // ---- tables ----
    s_inp[tid] = -1;
    s_ph[tid]  = __half_as_ushort(__int2half_rn(primes[tid]));
    for (int i = tid; i < OUT_DIM * R_NODES; i += 256) s_W[i] = readout_W[i];
    __syncthreads();
    if (tid < 32) {
        int nn = input_nodes[tid];
        s_innodes[tid] = nn;
        s_inp[nn] = (short)tid;
    }

    // ---- A fragments (Wp = Wres ? prime : 0), register-resident ----
    unsigned A[16][2][4];
    const int node_base = wid * 32;
    #pragma unroll
    for (int kt = 0; kt < 16; kt++) {
        #pragma unroll
        for (int mt = 0; mt < 2; mt++) {
            #pragma unroll
            for (int r = 0; r < 4; r++) {
                int row = node_base + mt * 16 + g + ((r & 1) ? 8 : 0);
                int k0  = kt * 16 + tg * 2 + ((r & 2) ? 8 : 0);
                unsigned h0 = Wres[row * 256 + k0]     ? (unsigned)s_ph[k0]     : 0u;
                unsigned h1 = Wres[row * 256 + k0 + 1] ? (unsigned)s_ph[k0 + 1] : 0u;
                A[kt][mt][r] = h0 | (h1 << 16);
            }
        }
    }

    // ---- init: rows s and s+4 = init_res state (both mirrors); then x_0 ----
    {
        __half v = init_res[tid] ? ONE : ZERO;
        #pragma unroll
        for (int s = 0; s < 8; s++) rb[0][s][tid] = v;
    }
    __syncthreads();
    if (tid < NPC * 32) {
        int s = tid >> 5, i = tid & 31;
        unsigned xb = (g_x_bits[(size_t)(mbase + s) * N_STEPS + 0] >> i) & 1u;
        __half v = xb ? ONE : ZERO;
        rb[0][s][s_innodes[i]] = v;
        rb[0][s + 4][s_innodes[i]] = v;
    }
    __syncthreads();

    // ---- per-lane gather constants ----
    const int mymt = tg >> 1;                    // which m-tile this lane gathers for
    const int n0 = node_base + mymt * 16 + g;    // lane's two nodes
    const int n1 = n0 + 8;
    const int sA = (tg & 1) * 2;                 // lane's two samples: sA, sA+1
    const bool i0 = (s_inp[n0] >= 0);
    const bool i1 = (s_inp[n1] >= 0);
    const unsigned* lp0 = g_lut_bits + (size_t)n0 * LUT_WORDS;
    const unsigned* lp1 = g_lut_bits + (size_t)n1 * LUT_WORDS;
    const int xs = tid >> 5, xi = tid & 31;      // x-overwrite role (threads < 128)
    const int xnode = (tid < NPC * 32) ? s_innodes[xi] : 0;
    const unsigned* xrow = g_x_bits + (size_t)(mbase + (xs & (NPC - 1))) * N_STEPS;

    // ---- 512 sequential steps, one barrier per step ----
    for (int t = 0; t < N_STEPS; t++) {
        const int p = t & 1;
        const bool last = (t == N_STEPS - 1);
        const __half (*cur)[RB_STRIDE] = rb[p];
        __half (*nxt)[RB_STRIDE] = rb[p ^ 1];

        unsigned xw = 0;
        if (!last && tid < NPC * 32) xw = xrow[t + 1];

        unsigned u[4], w[4];
        const bool own0 = (mymt == 0);
        const bool d0 = last || !i0;             // gather node n0?
        const bool d1 = last || !i1;

        // ---- phase A: mt0 chain (16 HMMA, 4-split accumulators) ----
        {
            float d[4][4];
            #pragma unroll
            for (int c = 0; c < 4; c++)
                #pragma unroll
                for (int e = 0; e < 4; e++) d[c][e] = (c == 0) ? MAGIC_F : 0.0f;
            #pragma unroll
            for (int kt = 0; kt < 16; kt++) {
                unsigned b0 = *(const unsigned*)&cur[g][kt * 16 + tg * 2];
                unsigned b1 = *(const unsigned*)&cur[g][kt * 16 + tg * 2 + 8];
                mma16816b(d[kt & 3], A[kt][0], b0, b1);
            }
            if (own0) {                          // extract + issue mt0 loads
                #pragma unroll
                for (int e = 0; e < 4; e++) {
                    float tot = (d[0][e] + d[1][e]) + (d[2][e] + d[3][e]);
                    u[e] = __float_as_uint(tot) & 0x7FFFFFu;
                }
                if (d0) { w[0] = lp0[u[0] >> 5]; w[1] = lp0[u[1] >> 5]; }
                if (d1) { w[2] = lp1[u[2] >> 5]; w[3] = lp1[u[3] >> 5]; }
            }
        }

        // ---- phase B: mt1 chain (overlaps mt0 L2 latency) ----
        {
            float d[4][4];
            #pragma unroll
            for (int c = 0; c < 4; c++)
                #pragma unroll
                for (int e = 0; e < 4; e++) d[c][e] = (c == 0) ? MAGIC_F : 0.0f;
            #pragma unroll
            for (int kt = 0; kt < 16; kt++) {
                unsigned b0 = *(const unsigned*)&cur[g][kt * 16 + tg * 2];
                unsigned b1 = *(const unsigned*)&cur[g][kt * 16 + tg * 2 + 8];
                mma16816b(d[kt & 3], A[kt][1], b0, b1);
            }
            if (!own0) {                         // extract + issue mt1 loads
                #pragma unroll
                for (int e = 0; e < 4; e++) {
                    float tot = (d[0][e] + d[1][e]) + (d[2][e] + d[3][e]);
                    u[e] = __float_as_uint(tot) & 0x7FFFFFu;
                }
                if (d0) { w[0] = lp0[u[0] >> 5]; w[1] = lp0[u[1] >> 5]; }
                if (d1) { w[2] = lp1[u[2] >> 5]; w[3] = lp1[u[3] >> 5]; }
            }
        }

        // ---- consume: mt0 lanes first (their loads have landed), then mt1 ----
        // element e -> node (e>>1 ? n1 : n0), sample sA + (e&1); mirror rows s, s+4
        #pragma unroll
        for (int pass = 0; pass < 2; pass++) {
            if ((pass == 0) == own0) {
                #pragma unroll
                for (int e = 0; e < 4; e++) {
                    bool de = (e & 2) ? d1 : d0;
                    if (de) {
                        int node = (e & 2) ? n1 : n0;
                        int samp = sA + (e & 1);
                        __half v = ((w[e] >> (u[e] & 31)) & 1u) ? ONE : ZERO;
                        nxt[samp][node] = v;
                        nxt[samp + 4][node] = v;
                    }
                }
            }
            if (pass == 0 && !last && tid < NPC * 32) {   // x_{t+1} between passes
                __half v = ((xw >> xi) & 1u) ? ONE : ZERO;
                nxt[xs][xnode] = v;
                nxt[xs + 4][xnode] = v;
            }
        }

        __syncthreads();
    }

    // ---- readout: warps 0-3, warp w -> sample w; final state in rb[0] ----
    if (wid < NPC) {
        float acc[OUT_DIM];
        #pragma unroll
        for (int o = 0; o < OUT_DIM; o++) acc[o] = 0.0f;
        #pragma unroll
        for (int kk = 0; kk < 8; kk++) {
            int k = lane + kk * 32;
            float rv = __half2float(rb[0][wid][k]);
            #pragma unroll
            for (int o = 0; o < OUT_DIM; o++)
                acc[o] += rv * s_W[o * R_NODES + k];
        }
        #pragma unroll
        for (int o = 0; o < OUT_DIM; o++) {
            #pragma unroll
            for (int off = 16; off; off >>= 1)
                acc[o] += __shfl_xor_sync(0xFFFFFFFFu, acc[o], off);
        }
        if (lane == 0) {
            #pragma unroll
            for (int o = 0; o < OUT_DIM; o++)
                out[(mbase + wid) * OUT_DIM + o] = acc[o] + readout_b[o];
        }
    }
}

// ---------------------------------------------------------------------------
// kernel_launch. Inputs: x, input_nodes, lut, W_res, primes, init_res,
// readout_W, readout_b (bool arrays delivered as int32).
// ---------------------------------------------------------------------------
extern "C" void kernel_launch(void* const* d_in, const int* in_sizes, int n_in,
                              void* d_out, int out_size) {
    const int*   x        = (const int*)d_in[0];
    const int*   in_nodes = (const int*)d_in[1];
    const int*   lut      = (const int*)d_in[2];
    const int*   Wres     = (const int*)d_in[3];
    const int*   primes   = (const int*)d_in[4];
    const int*   init_res = (const int*)d_in[5];
    const float* rW       = (const float*)d_in[6];
    const float* rb       = (const float*)d_in[7];
    float*       out      = (float*)d_out;

    pack_lut_kernel<<<(R_NODES * LUT_WORDS) / (32 * 8), 256>>>(lut);
    pack_x_kernel<<<(M_SAMP * N_STEPS) / 256, 256>>>(x);
    reservoir_kernel<<<N_CTA, 256>>>(in_nodes, Wres, primes, init_res, rW, rb, out);
}

// round 12
// speedup vs baseline: 2.4462x; 1.0991x over previous
#include <cuda_runtime.h>
#include <cuda_fp16.h>
#include <stdint.h>

#define R_NODES   256
#define N_STEPS   512
#define M_SAMP    512
#define OUT_DIM   10
#define LUT_WORDS 8192            // 2^18 bits / 32
#define NPC       4               // samples per CTA
#define N_CTA     (M_SAMP / NPC)  // 128 CTAs -> ~1 per SM
#define RB_STRIDE 264             // halfs per row: word banks (4g+tg) distinct
#define MAGIC_F   8388608.0f      // 2^23: accumulator mantissa low 23 bits == integer sum

// Scratch: __device__ globals (no allocation allowed)
__device__ unsigned g_lut_bits[R_NODES * LUT_WORDS]; // 8 MB bit-packed LUT

// ---------------------------------------------------------------------------
// Pack LUT (flat): word w, bit b = lut[w*32 + b]. MLP=32 load stage then ballots.
// ---------------------------------------------------------------------------
__global__ void pack_lut_kernel(const int* __restrict__ lut) {
    const int warp_g = (blockIdx.x * blockDim.x + threadIdx.x) >> 5;
    const int lane   = threadIdx.x & 31;
    const int w0     = warp_g * 32;
    const unsigned* src = (const unsigned*)lut;
    unsigned v[32];
    #pragma unroll
    for (int i = 0; i < 32; i++)
        v[i] = src[(size_t)(w0 + i) * 32 + lane];
    unsigned myw = 0;
    #pragma unroll
    for (int i = 0; i < 32; i++) {
        unsigned b = __ballot_sync(0xFFFFFFFFu, v[i] & 1u);
        if (i == lane) myw = b;
    }
    g_lut_bits[w0 + lane] = myw;
}

// ---------------------------------------------------------------------------
// m16n8k16 fp16 MMA, fp32 accumulate (exact for our integer ranges)
// ---------------------------------------------------------------------------
__device__ __forceinline__ void mma16816(float* d, const unsigned* a, unsigned b0, unsigned b1) {
    asm volatile(
        "mma.sync.aligned.m16n8k16.row.col.f32.f16.f16.f32 "
        "{%0,%1,%2,%3}, {%4,%5,%6,%7}, {%8,%9}, {%0,%1,%2,%3};\n"
        : "+f"(d[0]), "+f"(d[1]), "+f"(d[2]), "+f"(d[3])
        : "r"(a[0]), "r"(a[1]), "r"(a[2]), "r"(a[3]), "r"(b0), "r"(b1));
}

// ---------------------------------------------------------------------------
// Reservoir kernel: 128 CTAs x 256 threads, CTA b owns samples [4b, 4b+4).
// x is packed in the prologue (CTA-local). Warp w owns nodes [32w, 32w+32)
// (A in 128 regs). B rows hold samples [0,1,2,3,0,1,2,3] so ALL D columns are
// valid: lane (g,tg) gathers for nodes of m-tile (tg>>1), samples
// {2*(tg&1), 2*(tg&1)+1} -> 4 loads/lane. mt0-chain -> issue mt0 loads ->
// mt1-chain (overlaps L2 latency) -> issue mt1 loads -> consume + store.
// ---------------------------------------------------------------------------
__global__ void __launch_bounds__(256, 1)
reservoir_kernel(const int* __restrict__ x,
                 const int* __restrict__ input_nodes,
                 const int* __restrict__ Wres,
                 const int* __restrict__ primes,
                 const int* __restrict__ init_res,
                 const float* __restrict__ readout_W,
                 const float* __restrict__ readout_b,
                 float* __restrict__ out)
{
    __shared__ __half rb[2][8][RB_STRIDE];       // double-buffered; rows s and s+4 mirror
    __shared__ unsigned s_x[NPC][N_STEPS];       // packed inputs, bit i = feature i
    __shared__ short s_inp[R_NODES];
    __shared__ int s_innodes[32];
    __shared__ unsigned short s_ph[R_NODES];
    __shared__ float s_W[OUT_DIM * R_NODES];

    const int tid  = threadIdx.x;
    const int wid  = tid >> 5;
    const int lane = tid & 31;
    const int g    = lane >> 2;
    const int tg   = lane & 3;
    const int mbase = blockIdx.x * NPC;
    const __half ONE  = __ushort_as_half(0x3C00);
    const __half ZERO = __ushort_as_half(0x0000);

    // ---- tables ----
    s_inp[tid] = -1;
    s_ph[tid]  = __half_as_ushort(__int2half_rn(primes[tid]));
    for (int i = tid; i < OUT_DIM * R_NODES; i += 256) s_W[i] = readout_W[i];
    __syncthreads();
    if (tid < 32) {
        int nn = input_nodes[tid];
        s_innodes[tid] = nn;
        s_inp[nn] = (short)tid;
    }

    // ---- pack this CTA's x slice: NPC*512 words, 32 ints each ----
    // thread handles words w = tid, tid+256, ... (NPC*512 = 2048 words)
    for (int w = tid; w < NPC * N_STEPS; w += 256) {
        int s = w >> 9;               // local sample
        int t = w & (N_STEPS - 1);    // step
        const uint4* p = (const uint4*)(x + ((size_t)(mbase + s) * N_STEPS + t) * 32);
        unsigned word = 0;
        #pragma unroll
        for (int j = 0; j < 8; j++) {
            uint4 v = p[j];
            word |= (v.x & 1u) << (4 * j + 0);
            word |= (v.y & 1u) << (4 * j + 1);
            word |= (v.z & 1u) << (4 * j + 2);
            word |= (v.w & 1u) << (4 * j + 3);
        }
        s_x[s][t] = word;
    }

    // ---- A fragments (Wp = Wres ? prime : 0), register-resident ----
    unsigned A[16][2][4];
    const int node_base = wid * 32;
    #pragma unroll
    for (int kt = 0; kt < 16; kt++) {
        #pragma unroll
        for (int mt = 0; mt < 2; mt++) {
            #pragma unroll
            for (int r = 0; r < 4; r++) {
                int row = node_base + mt * 16 + g + ((r & 1) ? 8 : 0);
                int k0  = kt * 16 + tg * 2 + ((r & 2) ? 8 : 0);
                unsigned h0 = Wres[row * 256 + k0]     ? (unsigned)s_ph[k0]     : 0u;
                unsigned h1 = Wres[row * 256 + k0 + 1] ? (unsigned)s_ph[k0 + 1] : 0u;
                A[kt][mt][r] = h0 | (h1 << 16);
            }
        }
    }

    // ---- init: rows s and s+4 = init_res state (both mirrors); then x_0 ----
    {
        __half v = init_res[tid] ? ONE : ZERO;
        #pragma unroll
        for (int s = 0; s < 8; s++) rb[0][s][tid] = v;
    }
    __syncthreads();
    if (tid < NPC * 32) {
        int s = tid >> 5, i = tid & 31;
        unsigned xb = (s_x[s][0] >> i) & 1u;
        __half v = xb ? ONE : ZERO;
        rb[0][s][s_innodes[i]] = v;
        rb[0][s + 4][s_innodes[i]] = v;
    }
    __syncthreads();

    // ---- per-lane gather constants ----
    const int mymt = tg >> 1;                    // which m-tile this lane gathers for
    const int n0 = node_base + mymt * 16 + g;    // lane's two nodes
    const int n1 = n0 + 8;
    const int sA = (tg & 1) * 2;                 // lane's two samples: sA, sA+1
    const bool i0 = (s_inp[n0] >= 0);
    const bool i1 = (s_inp[n1] >= 0);
    const unsigned* lp0 = g_lut_bits + (size_t)n0 * LUT_WORDS;
    const unsigned* lp1 = g_lut_bits + (size_t)n1 * LUT_WORDS;
    const int xs = tid >> 5, xi = tid & 31;      // x-overwrite role (threads < 128)
    const int xnode = (tid < NPC * 32) ? s_innodes[xi] : 0;

    // ---- 512 sequential steps, one barrier per step ----
    for (int t = 0; t < N_STEPS; t++) {
        const int p = t & 1;
        const bool last = (t == N_STEPS - 1);
        const __half (*cur)[RB_STRIDE] = rb[p];
        __half (*nxt)[RB_STRIDE] = rb[p ^ 1];

        unsigned xw = 0;
        if (!last && tid < NPC * 32) xw = s_x[xs][t + 1];

        unsigned u[4], w[4];
        const bool own0 = (mymt == 0);
        const bool d0 = last || !i0;             // gather node n0?
        const bool d1 = last || !i1;

        // ---- phase A: mt0 chain (16 HMMA, 4-split accumulators) ----
        {
            float d[4][4];
            #pragma unroll
            for (int c = 0; c < 4; c++)
                #pragma unroll
                for (int e = 0; e < 4; e++) d[c][e] = (c == 0) ? MAGIC_F : 0.0f;
            #pragma unroll
            for (int kt = 0; kt < 16; kt++) {
                unsigned b0 = *(const unsigned*)&cur[g][kt * 16 + tg * 2];
                unsigned b1 = *(const unsigned*)&cur[g][kt * 16 + tg * 2 + 8];
                mma16816(d[kt & 3], A[kt][0], b0, b1);
            }
            if (own0) {                          // extract + issue mt0 loads
                #pragma unroll
                for (int e = 0; e < 4; e++) {
                    float tot = (d[0][e] + d[1][e]) + (d[2][e] + d[3][e]);
                    u[e] = __float_as_uint(tot) & 0x7FFFFFu;
                }
                if (d0) { w[0] = __ldg(&lp0[u[0] >> 5]); w[1] = __ldg(&lp0[u[1] >> 5]); }
                if (d1) { w[2] = __ldg(&lp1[u[2] >> 5]); w[3] = __ldg(&lp1[u[3] >> 5]); }
            }
        }

        // ---- phase B: mt1 chain (overlaps mt0 L2 latency) ----
        {
            float d[4][4];
            #pragma unroll
            for (int c = 0; c < 4; c++)
                #pragma unroll
                for (int e = 0; e < 4; e++) d[c][e] = (c == 0) ? MAGIC_F : 0.0f;
            #pragma unroll
            for (int kt = 0; kt < 16; kt++) {
                unsigned b0 = *(const unsigned*)&cur[g][kt * 16 + tg * 2];
                unsigned b1 = *(const unsigned*)&cur[g][kt * 16 + tg * 2 + 8];
                mma16816(d[kt & 3], A[kt][1], b0, b1);
            }
            if (!own0) {                         // extract + issue mt1 loads
                #pragma unroll
                for (int e = 0; e < 4; e++) {
                    float tot = (d[0][e] + d[1][e]) + (d[2][e] + d[3][e]);
                    u[e] = __float_as_uint(tot) & 0x7FFFFFu;
                }
                if (d0) { w[0] = __ldg(&lp0[u[0] >> 5]); w[1] = __ldg(&lp0[u[1] >> 5]); }
                if (d1) { w[2] = __ldg(&lp1[u[2] >> 5]); w[3] = __ldg(&lp1[u[3] >> 5]); }
            }
        }

        // ---- consume: mt0 lanes first (their loads have landed), then mt1 ----
        #pragma unroll
        for (int pass = 0; pass < 2; pass++) {
            if ((pass == 0) == own0) {
                #pragma unroll
                for (int e = 0; e < 4; e++) {
                    bool de = (e & 2) ? d1 : d0;
                    if (de) {
                        int node = (e & 2) ? n1 : n0;
                        int samp = sA + (e & 1);
                        __half v = ((w[e] >> (u[e] & 31)) & 1u) ? ONE : ZERO;
                        nxt[samp][node] = v;
                        nxt[samp + 4][node] = v;
                    }
                }
            }
            if (pass == 0 && !last && tid < NPC * 32) {   // x_{t+1} between passes
                __half v = ((xw >> xi) & 1u) ? ONE : ZERO;
                nxt[xs][xnode] = v;
                nxt[xs + 4][xnode] = v;
            }
        }

        __syncthreads();
    }

    // ---- readout: warps 0-3, warp w -> sample w; final state in rb[0] ----
    if (wid < NPC) {
        float acc[OUT_DIM];
        #pragma unroll
        for (int o = 0; o < OUT_DIM; o++) acc[o] = 0.0f;
        #pragma unroll
        for (int kk = 0; kk < 8; kk++) {
            int k = lane + kk * 32;
            float rv = __half2float(rb[0][wid][k]);
            #pragma unroll
            for (int o = 0; o < OUT_DIM; o++)
                acc[o] += rv * s_W[o * R_NODES + k];
        }
        #pragma unroll
        for (int o = 0; o < OUT_DIM; o++) {
            #pragma unroll
            for (int off = 16; off; off >>= 1)
                acc[o] += __shfl_xor_sync(0xFFFFFFFFu, acc[o], off);
        }
        if (lane == 0) {
            #pragma unroll
            for (int o = 0; o < OUT_DIM; o++)
                out[(mbase + wid) * OUT_DIM + o] = acc[o] + readout_b[o];
        }
    }
}

// ---------------------------------------------------------------------------
// kernel_launch. Inputs: x, input_nodes, lut, W_res, primes, init_res,
// readout_W, readout_b (bool arrays delivered as int32). Two launches per
// call: pack_lut then reservoir (x packing fused into the reservoir).
// ---------------------------------------------------------------------------
extern "C" void kernel_launch(void* const* d_in, const int* in_sizes, int n_in,
                              void* d_out, int out_size) {
    const int*   x        = (const int*)d_in[0];
    const int*   in_nodes = (const int*)d_in[1];
    const int*   lut      = (const int*)d_in[2];
    const int*   Wres     = (const int*)d_in[3];
    const int*   primes   = (const int*)d_in[4];
    const int*   init_res = (const int*)d_in[5];
    const float* rW       = (const float*)d_in[6];
    const float* rb       = (const float*)d_in[7];
    float*       out      = (float*)d_out;

    pack_lut_kernel<<<(R_NODES * LUT_WORDS) / (32 * 8), 256>>>(lut);
    reservoir_kernel<<<N_CTA, 256>>>(x, in_nodes, Wres, primes, init_res, rW, rb, out);
}